// round 15
// baseline (speedup 1.0000x reference)
#include <cuda_runtime.h>

#define NN 50000
#define EE 800000
#define CSRB 148                    // CSR-role blocks (== #SMs, wave-1 resident)
#define NSEG 196                    // ceil(NN/256) scan segments
#define TS 40                       // smem tile row stride (bf16 elems), 32 data + 8 pad

typedef unsigned long long ull;

// ---------------- device scratch (static only) ----------------
__device__ int    d_is64;
__device__ int    d_cnt[NN];
__device__ int    d_cursor[NN];
__device__ int    d_rowptr[NN + 1];
__device__ int    d_col[EE];
__device__ int    d_bsum[NSEG];
__device__ unsigned d_gbar[4];      // monotonic epoch barriers (zero-init at load)
__device__ float4 d_t1l[NN * 32];  // [NN,128] = x @ W1l   (gathered)
__device__ float4 d_t1r[NN * 32];  // [NN,128] = x @ W1r   (self)
__device__ float4 d_h1[NN * 32];   // [NN,128]
__device__ float4 d_t2l[NN * 16];  // [NN,64]  = h1 @ W2l  (gathered)
__device__ float4 d_t2r[NN * 16];  // [NN,64]  = h1 @ W2r  (self)
__device__ float4 d_y[NN * 16];    // [NN,64]  (h2@Wg)*dinv
// transposed bf16-split weights: WT[n][k] = W[k][n]
__device__ uint4  d_wt1h4[256 * 128 / 8];
__device__ uint4  d_wt1lo4[256 * 128 / 8];
__device__ uint4  d_wt2h4[128 * 128 / 8];
__device__ uint4  d_wt2lo4[128 * 128 / 8];

// ---------------- helpers ----------------
__device__ __forceinline__ unsigned short bf16rne(float f) {
    unsigned u = __float_as_uint(f);
    unsigned r = u + 0x7FFFu + ((u >> 16) & 1u);
    return (unsigned short)(r >> 16);
}
__device__ __forceinline__ float bf16tof(unsigned short h) {
    return __uint_as_float((unsigned)h << 16);
}
__device__ __forceinline__ unsigned smem_u32(const void* p) {
    unsigned a;
    asm("{ .reg .u64 t; cvta.to.shared.u64 t, %1; cvt.u32.u64 %0, t; }" : "=r"(a) : "l"(p));
    return a;
}
__device__ __forceinline__ void ldm_x4(unsigned (&r)[4], unsigned addr) {
    asm volatile("ldmatrix.sync.aligned.m8n8.x4.shared.b16 {%0,%1,%2,%3}, [%4];"
                 : "=r"(r[0]), "=r"(r[1]), "=r"(r[2]), "=r"(r[3]) : "r"(addr));
}
__device__ __forceinline__ void mma16816(float (&d)[4], const unsigned (&a)[4],
                                         unsigned b0, unsigned b1) {
    asm volatile(
        "mma.sync.aligned.m16n8k16.row.col.f32.bf16.bf16.f32 "
        "{%0,%1,%2,%3}, {%4,%5,%6,%7}, {%8,%9}, {%0,%1,%2,%3};"
        : "+f"(d[0]), "+f"(d[1]), "+f"(d[2]), "+f"(d[3])
        : "r"(a[0]), "r"(a[1]), "r"(a[2]), "r"(a[3]), "r"(b0), "r"(b1));
}
// monotonic-epoch grid barrier among the CSRB CSR-role blocks only
__device__ __forceinline__ void grid_bar(int id) {
    __syncthreads();
    if (threadIdx.x == 0) {
        __threadfence();
        unsigned old = atomicAdd(&d_gbar[id], 1u);
        unsigned target = (old / (unsigned)CSRB + 1u) * (unsigned)CSRB;
        unsigned v;
        do {
            asm volatile("ld.global.acquire.gpu.b32 %0, [%1];" : "=r"(v) : "l"(&d_gbar[id]));
        } while (v < target);
    }
    __syncthreads();
}

__device__ __forceinline__ int edge_id(const void* ei, int which, int e) {
    if (d_is64) return (int)((const long long*)ei)[(size_t)which * EE + e];
    return ((const int*)ei)[(size_t)which * EE + e];
}

// -------- weight prep: transpose + bf16 hi/lo split (WT[n][k] = W[k][n]) ---------
__global__ void k_prep_w(const float* __restrict__ W1l, const float* __restrict__ W1r,
                         const float* __restrict__ W2l, const float* __restrict__ W2r) {
    int idx = blockIdx.x * blockDim.x + threadIdx.x;
    if (idx < 256 * 128) {
        int n = idx >> 7, k = idx & 127;
        float w = (n < 128) ? W1l[k * 128 + n] : W1r[k * 128 + (n - 128)];
        unsigned short h = bf16rne(w);
        ((unsigned short*)d_wt1h4)[idx] = h;
        ((unsigned short*)d_wt1lo4)[idx] = bf16rne(w - bf16tof(h));
    }
    if (idx < 128 * 128) {
        int n = idx >> 7, k = idx & 127;
        float w = (n < 64) ? W2l[k * 64 + n] : W2r[k * 64 + (n - 64)];
        unsigned short h = bf16rne(w);
        ((unsigned short*)d_wt2h4)[idx] = h;
        ((unsigned short*)d_wt2lo4)[idx] = bf16rne(w - bf16tof(h));
    }
}

// ---------------- mma.sync bf16-split GEMM body (shared by fused l1 + l2) ----------------
// which==0: D[NN,256] = x @ [W1l|W1r]; nBase=0 -> t1l, 128 -> t1r
// which==1: D[NN,128] = h1 @ [W2l|W2r]; cols<64 -> t2l, else t2r
__device__ __forceinline__ void gemm_body(const float* __restrict__ A,
                                          const unsigned short* __restrict__ WTh,
                                          const unsigned short* __restrict__ WTl,
                                          int which, int rowBase, int nBase) {
    __shared__ __align__(16) unsigned short sAh[128 * TS];
    __shared__ __align__(16) unsigned short sAl[128 * TS];
    __shared__ __align__(16) unsigned short sBh[128 * TS];
    __shared__ __align__(16) unsigned short sBl[128 * TS];

    int tid = threadIdx.x;
    int wid = tid >> 5;
    int lane = tid & 31;
    int wm = wid >> 2;
    int wn = wid & 3;

    float acc[4][4][4];
#pragma unroll
    for (int mi = 0; mi < 4; mi++)
#pragma unroll
        for (int ni = 0; ni < 4; ni++)
#pragma unroll
            for (int q = 0; q < 4; q++) acc[mi][ni][q] = 0.f;

    unsigned bAh = smem_u32(sAh), bAl = smem_u32(sAl);
    unsigned bBh = smem_u32(sBh), bBl = smem_u32(sBl);

    int frow = tid >> 1;
    int fcol = (tid & 1) * 16;
    int grow = rowBase + frow;

    for (int kk = 0; kk < 128; kk += 32) {
        {
            float t[16];
            if (grow < NN) {
                const float4* src = (const float4*)(A + (size_t)grow * 128 + kk + fcol);
#pragma unroll
                for (int i = 0; i < 4; i++) {
                    float4 v = src[i];
                    t[i * 4 + 0] = v.x; t[i * 4 + 1] = v.y;
                    t[i * 4 + 2] = v.z; t[i * 4 + 3] = v.w;
                }
            } else {
#pragma unroll
                for (int i = 0; i < 16; i++) t[i] = 0.f;
            }
            unsigned short hb[16], lb[16];
#pragma unroll
            for (int i = 0; i < 16; i++) {
                hb[i] = bf16rne(t[i]);
                lb[i] = bf16rne(t[i] - bf16tof(hb[i]));
            }
            uint4* dh = (uint4*)&sAh[frow * TS + fcol];
            uint4* dl = (uint4*)&sAl[frow * TS + fcol];
            dh[0] = ((uint4*)hb)[0]; dh[1] = ((uint4*)hb)[1];
            dl[0] = ((uint4*)lb)[0]; dl[1] = ((uint4*)lb)[1];
        }
        {
            const uint4* sh = (const uint4*)(WTh + (size_t)(nBase + frow) * 128 + kk + fcol);
            const uint4* sl = (const uint4*)(WTl + (size_t)(nBase + frow) * 128 + kk + fcol);
            uint4* dh = (uint4*)&sBh[frow * TS + fcol];
            uint4* dl = (uint4*)&sBl[frow * TS + fcol];
            dh[0] = sh[0]; dh[1] = sh[1];
            dl[0] = sl[0]; dl[1] = sl[1];
        }
        __syncthreads();

#pragma unroll
        for (int ks = 0; ks < 32; ks += 16) {
            unsigned aH[4][4], aL[4][4];
#pragma unroll
            for (int mi = 0; mi < 4; mi++) {
                int row = wm * 64 + mi * 16 + (lane & 15);
                int col = ks + (lane >> 4) * 8;
                unsigned off = (unsigned)(row * TS + col) * 2;
                ldm_x4(aH[mi], bAh + off);
                ldm_x4(aL[mi], bAl + off);
            }
            unsigned bH[4][2], bL[4][2];
#pragma unroll
            for (int nip = 0; nip < 4; nip += 2) {
                int nrow = wn * 32 + nip * 8 + ((lane >> 4) & 1) * 8 + (lane & 7);
                int kcol = ks + ((lane >> 3) & 1) * 8;
                unsigned off = (unsigned)(nrow * TS + kcol) * 2;
                unsigned r[4];
                ldm_x4(r, bBh + off);
                bH[nip][0] = r[0]; bH[nip][1] = r[1];
                bH[nip + 1][0] = r[2]; bH[nip + 1][1] = r[3];
                ldm_x4(r, bBl + off);
                bL[nip][0] = r[0]; bL[nip][1] = r[1];
                bL[nip + 1][0] = r[2]; bL[nip + 1][1] = r[3];
            }
#pragma unroll
            for (int mi = 0; mi < 4; mi++)
#pragma unroll
                for (int ni = 0; ni < 4; ni++) {
                    mma16816(acc[mi][ni], aH[mi], bH[ni][0], bH[ni][1]);
                    mma16816(acc[mi][ni], aL[mi], bH[ni][0], bH[ni][1]);
                    mma16816(acc[mi][ni], aH[mi], bL[ni][0], bL[ni][1]);
                }
        }
        __syncthreads();
    }

    float* outL = which ? (float*)d_t2l : (float*)d_t1l;
    float* outR = which ? (float*)d_t2r : (float*)d_t1r;
#pragma unroll
    for (int mi = 0; mi < 4; mi++) {
        int r0 = rowBase + wm * 64 + mi * 16 + (lane >> 2);
#pragma unroll
        for (int ni = 0; ni < 4; ni++) {
            int cl = wn * 32 + ni * 8 + (lane & 3) * 2;
            if (!which) {
                float* dst = (nBase == 0) ? outL : outR;
                if (r0 < NN)
                    *(float2*)(dst + (size_t)r0 * 128 + cl) =
                        make_float2(acc[mi][ni][0], acc[mi][ni][1]);
                if (r0 + 8 < NN)
                    *(float2*)(dst + (size_t)(r0 + 8) * 128 + cl) =
                        make_float2(acc[mi][ni][2], acc[mi][ni][3]);
            } else {
                float* base = (cl < 64) ? (outL + cl) : (outR + (cl - 64));
                if (r0 < NN)
                    *(float2*)(base + (size_t)r0 * 64) =
                        make_float2(acc[mi][ni][0], acc[mi][ni][1]);
                if (r0 + 8 < NN)
                    *(float2*)(base + (size_t)(r0 + 8) * 64) =
                        make_float2(acc[mi][ni][2], acc[mi][ni][3]);
            }
        }
    }
}

// ---------------- fused kernel: CSR build (blocks 0..147) + layer1 GEMM (rest) ------------
// NOTE: no launch_bounds here — R13 showed the 128-reg cap costs ~7us on this kernel.
__global__ void k_fused(const float* __restrict__ x, const void* __restrict__ ei) {
    int bid = blockIdx.x;
    if (bid >= CSRB) {
        int gb = bid - CSRB;
        gemm_body(x, (const unsigned short*)d_wt1h4, (const unsigned short*)d_wt1lo4,
                  0, (gb >> 1) * 128, (gb & 1) * 128);
        return;
    }
    // ---------------- CSR role ----------------
    __shared__ int s[256];
    int tid = threadIdx.x;
    const int NT = CSRB * 256;
    int g = bid * 256 + tid;

    // phase A: zero counters; block 0 probes edge dtype
    for (int i = g; i < NN; i += NT) { d_cnt[i] = 0; d_cursor[i] = 0; }
    if (bid == 0) {
        __shared__ int nonzero;
        if (tid == 0) nonzero = 0;
        __syncthreads();
        const int* e32 = (const int*)ei;
        for (int j = tid; j < 4096; j += 256)
            if (e32[2 * j + 1] != 0) nonzero = 1;
        __syncthreads();
        if (tid == 0) d_is64 = (nonzero == 0) ? 1 : 0;
    }
    grid_bar(0);

    // phase B: degree count
    for (int e = g; e < EE; e += NT)
        atomicAdd(&d_cnt[edge_id(ei, 1, e)], 1);
    grid_bar(1);

    // phase C: per-segment exclusive scan (segments of 256)
    for (int seg = bid; seg < NSEG; seg += CSRB) {
        int i = seg * 256 + tid;
        int v = (i < NN) ? d_cnt[i] : 0;
        s[tid] = v;
        __syncthreads();
        for (int off = 1; off < 256; off <<= 1) {
            int t2 = (tid >= off) ? s[tid - off] : 0;
            __syncthreads();
            s[tid] += t2;
            __syncthreads();
        }
        if (i < NN) d_rowptr[i] = s[tid] - v;
        if (tid == 255) d_bsum[seg] = s[255];
        __syncthreads();
    }
    grid_bar(2);

    // phase D: redundant scan of segment sums + apply prefix
    s[tid] = (tid < NSEG) ? d_bsum[tid] : 0;
    __syncthreads();
    for (int off = 1; off < 256; off <<= 1) {
        int t2 = (tid >= off) ? s[tid - off] : 0;
        __syncthreads();
        s[tid] += t2;
        __syncthreads();
    }
    for (int seg = bid; seg < NSEG; seg += CSRB) {
        int prefix = (seg == 0) ? 0 : s[seg - 1];
        int i = seg * 256 + tid;
        if (i < NN) d_rowptr[i] += prefix;
    }
    if (bid == 0 && tid == 0) d_rowptr[NN] = EE;
    grid_bar(3);

    // phase E: fill columns
    for (int e = g; e < EE; e += NT) {
        int d = edge_id(ei, 1, e);
        int sc = edge_id(ei, 0, e);
        int p = atomicAdd(&d_cursor[d], 1);
        d_col[d_rowptr[d] + p] = sc;
    }
}

// ---------------- layer2 GEMM launcher (occ-2 cap: measured win on this kernel) -----------
__global__ void __launch_bounds__(256, 2) k_gemm_l2() {
    gemm_body((const float*)d_h1, (const unsigned short*)d_wt2h4,
              (const unsigned short*)d_wt2lo4, 1, blockIdx.x * 128, 0);
}

// ---------- layer1 agg: h1 = relu(mean_nbr(t1l) + t1r[self] + b1l); warp per node ---------
__global__ void k_agg1(const float* __restrict__ b1l) {
    int idx = blockIdx.x * blockDim.x + threadIdx.x;
    int node = idx >> 5;
    int lane = idx & 31;
    if (node >= NN) return;
    int beg = d_rowptr[node], end = d_rowptr[node + 1];
    float4 acc = make_float4(0.f, 0.f, 0.f, 0.f);
    for (int j = beg; j < end; j++) {
        int s = d_col[j];
        float4 v = d_t1l[(size_t)s * 32 + lane];
        acc.x += v.x; acc.y += v.y; acc.z += v.z; acc.w += v.w;
    }
    int c = end - beg;
    float inv = 1.0f / (float)(c > 0 ? c : 1);
    float4 self = d_t1r[(size_t)node * 32 + lane];
    float4 b = ((const float4*)b1l)[lane];
    float4 o;
    o.x = fmaxf(acc.x * inv + self.x + b.x, 0.f);
    o.y = fmaxf(acc.y * inv + self.y + b.y, 0.f);
    o.z = fmaxf(acc.z * inv + self.z + b.z, 0.f);
    o.w = fmaxf(acc.w * inv + self.w + b.w, 0.f);
    d_h1[(size_t)node * 32 + lane] = o;
}

// ---- fused agg2 + softmax + GCN GEMM, fat grid preserved: 8 nodes/block, warp/node ----
// phase1 (warp w -> node): h2row = softmax(mean_nbr(t2l) + t2r[self] + b2l) -> smem
// phase2 (thread -> row r, colpair c): y[node][c..c+1] = (h2row @ Wg) * dinv[node]
__global__ void __launch_bounds__(256) k_agg2gcn(const float* __restrict__ b2l,
                                                 const float* __restrict__ Wg) {
    __shared__ float Wgs[64][66];    // 66 keeps float2 alignment + declusters banks
    __shared__ float h2s[8 * 64];
    int tid = threadIdx.x;
    int wid = tid >> 5, lane = tid & 31;
    int nodeBase = blockIdx.x * 8;

    // load Wg tile (64x64 floats = 2048 float2; 256 threads x 8 iters x 1 float2)
#pragma unroll
    for (int it = 0; it < 8; it++) {
        int idx = tid + it * 256;          // 0..2047
        int r = idx >> 5;                  // 0..63
        int c2 = (idx & 31) * 2;           // 0..62
        *(float2*)&Wgs[r][c2] = *(const float2*)(Wg + (size_t)r * 64 + c2);
    }

    // ---- phase 1: gather + bias + softmax into smem (warp per node) ----
    {
        int node = nodeBase + wid;
        float2 o = make_float2(0.f, 0.f);
        if (node < NN) {
            int beg = d_rowptr[node], end = d_rowptr[node + 1];
            const float2* t2 = (const float2*)d_t2l;
            float ax = 0.f, ay = 0.f;
            for (int j = beg; j < end; j++) {
                int sc = d_col[j];
                float2 v = t2[(size_t)sc * 32 + lane];
                ax += v.x; ay += v.y;
            }
            float inv = 1.0f / (float)((end - beg) > 0 ? (end - beg) : 1);
            float2 self = ((const float2*)d_t2r)[(size_t)node * 32 + lane];
            float2 b = ((const float2*)b2l)[lane];
            float vx = ax * inv + self.x + b.x;
            float vy = ay * inv + self.y + b.y;
            float m = fmaxf(vx, vy);
            for (int o2 = 16; o2 > 0; o2 >>= 1) m = fmaxf(m, __shfl_xor_sync(0xffffffffu, m, o2));
            float ex = __expf(vx - m), ey = __expf(vy - m);
            float sum = ex + ey;
            for (int o2 = 16; o2 > 0; o2 >>= 1) sum += __shfl_xor_sync(0xffffffffu, sum, o2);
            float is = 1.0f / sum;
            o = make_float2(ex * is, ey * is);
        }
        *(float2*)&h2s[wid * 64 + lane * 2] = o;
    }
    __syncthreads();

    // ---- phase 2: 8x64 @ 64x64 FFMA; thread = (row, 2 cols) ----
    {
        int r = tid >> 5;              // 0..7
        int c2 = (tid & 31) * 2;       // 0..62
        float a0 = 0.f, a1 = 0.f;
#pragma unroll 16
        for (int k = 0; k < 64; k++) {
            float h = h2s[r * 64 + k];             // broadcast within row group
            float2 w = *(const float2*)&Wgs[k][c2];
            a0 += h * w.x;
            a1 += h * w.y;
        }
        int node = nodeBase + r;
        if (node < NN) {
            float dinv = rsqrtf((float)(d_cnt[node] + 1));
            ((float2*)d_y)[(size_t)node * 32 + (c2 >> 1)] = make_float2(a0 * dinv, a1 * dinv);
        }
    }
}

// ---------------- GCN aggregation: out[i] = dinv[i]*(y[i] + sum_nbr y[j]) + bg ------------
__global__ void k_gcn_agg(const float* __restrict__ bg, float* __restrict__ out) {
    int idx = blockIdx.x * blockDim.x + threadIdx.x;
    int node = idx >> 4;
    int lane = idx & 15;
    if (node >= NN) return;
    float4 acc = d_y[(size_t)node * 16 + lane];
    int beg = d_rowptr[node], end = d_rowptr[node + 1];
    for (int j = beg; j < end; j++) {
        int s = d_col[j];
        float4 v = d_y[(size_t)s * 16 + lane];
        acc.x += v.x; acc.y += v.y; acc.z += v.z; acc.w += v.w;
    }
    float dinv = rsqrtf((float)(d_cnt[node] + 1));
    float4 b = ((const float4*)bg)[lane];
    float4 o;
    o.x = acc.x * dinv + b.x;
    o.y = acc.y * dinv + b.y;
    o.z = acc.z * dinv + b.z;
    o.w = acc.w * dinv + b.w;
    ((float4*)out)[(size_t)node * 16 + lane] = o;
}

// ---------------- launch ----------------
extern "C" void kernel_launch(void* const* d_in, const int* in_sizes, int n_in,
                              void* d_out, int out_size) {
    const float* x = (const float*)d_in[0];
    const void* ei = d_in[1];
    const float* W1l = (const float*)d_in[2];
    const float* b1l = (const float*)d_in[3];
    const float* W1r = (const float*)d_in[4];
    const float* W2l = (const float*)d_in[5];
    const float* b2l = (const float*)d_in[6];
    const float* W2r = (const float*)d_in[7];
    const float* Wg  = (const float*)d_in[8];
    const float* bg  = (const float*)d_in[9];
    float* out = (float*)d_out;

    const int GT = (NN + 127) / 128;  // 391

    // weight prep, then fused CSR-build + layer1 GEMM (CSR hidden under GEMM)
    k_prep_w<<<128, 256>>>(W1l, W1r, W2l, W2r);
    k_fused<<<CSRB + GT * 2, 256>>>(x, ei);

    // layer 1 epilogue: fused agg + bias + relu (fat grid — gathers need parallelism)
    k_agg1<<<(NN * 32 + 255) / 256, 256>>>(b1l);

    // layer 2: mma GEMM (occ-2 cap), then fused agg + softmax + GCN GEMM (fat grid)
    k_gemm_l2<<<GT, 256>>>();
    k_agg2gcn<<<(NN + 7) / 8, 256>>>(b2l, Wg);

    // final normalized aggregation + bias
    k_gcn_agg<<<(NN * 16 + 255) / 256, 256>>>(bg, out);
}

// round 16
// speedup vs baseline: 1.1016x; 1.1016x over previous
#include <cuda_runtime.h>
#include <cuda_fp16.h>

#define NN 50000
#define EE 800000
#define CSRB 148                    // CSR-role blocks (== #SMs, wave-1 resident)
#define NSEG 196                    // ceil(NN/256) scan segments
#define TS 40                       // smem tile row stride (bf16 elems), 32 data + 8 pad

typedef unsigned long long ull;

// ---------------- device scratch (static only) ----------------
__device__ int    d_is64;
__device__ int    d_cnt[NN];
__device__ int    d_cursor[NN];
__device__ int    d_rowptr[NN + 1];
__device__ int    d_col[EE];
__device__ int    d_bsum[NSEG];
__device__ unsigned d_gbar[4];      // monotonic epoch barriers (zero-init at load)
__device__ __half2 d_t1l_h[NN * 64]; // [NN,128] fp16 = x @ W1l  (gathered -> half traffic)
__device__ float4 d_t1r[NN * 32];   // [NN,128] fp32 = x @ W1r  (self)
__device__ float4 d_h1[NN * 32];    // [NN,128]
__device__ __half2 d_t2l_h[NN * 32]; // [NN,64] fp16 = h1 @ W2l (gathered)
__device__ float4 d_t2r[NN * 16];   // [NN,64]  fp32 = h1 @ W2r (self)
__device__ float4 d_h2[NN * 16];    // [NN,64]  softmax output
__device__ float4 d_y[NN * 16];     // [NN,64]  (h2@Wg)*dinv
// transposed bf16-split weights: WT[n][k] = W[k][n]
__device__ uint4  d_wt1h4[256 * 128 / 8];
__device__ uint4  d_wt1lo4[256 * 128 / 8];
__device__ uint4  d_wt2h4[128 * 128 / 8];
__device__ uint4  d_wt2lo4[128 * 128 / 8];

// ---------------- helpers ----------------
__device__ __forceinline__ unsigned short bf16rne(float f) {
    unsigned u = __float_as_uint(f);
    unsigned r = u + 0x7FFFu + ((u >> 16) & 1u);
    return (unsigned short)(r >> 16);
}
__device__ __forceinline__ float bf16tof(unsigned short h) {
    return __uint_as_float((unsigned)h << 16);
}
__device__ __forceinline__ unsigned smem_u32(const void* p) {
    unsigned a;
    asm("{ .reg .u64 t; cvta.to.shared.u64 t, %1; cvt.u32.u64 %0, t; }" : "=r"(a) : "l"(p));
    return a;
}
__device__ __forceinline__ void ldm_x4(unsigned (&r)[4], unsigned addr) {
    asm volatile("ldmatrix.sync.aligned.m8n8.x4.shared.b16 {%0,%1,%2,%3}, [%4];"
                 : "=r"(r[0]), "=r"(r[1]), "=r"(r[2]), "=r"(r[3]) : "r"(addr));
}
__device__ __forceinline__ void mma16816(float (&d)[4], const unsigned (&a)[4],
                                         unsigned b0, unsigned b1) {
    asm volatile(
        "mma.sync.aligned.m16n8k16.row.col.f32.bf16.bf16.f32 "
        "{%0,%1,%2,%3}, {%4,%5,%6,%7}, {%8,%9}, {%0,%1,%2,%3};"
        : "+f"(d[0]), "+f"(d[1]), "+f"(d[2]), "+f"(d[3])
        : "r"(a[0]), "r"(a[1]), "r"(a[2]), "r"(a[3]), "r"(b0), "r"(b1));
}
// monotonic-epoch grid barrier among the CSRB CSR-role blocks only
__device__ __forceinline__ void grid_bar(int id) {
    __syncthreads();
    if (threadIdx.x == 0) {
        __threadfence();
        unsigned old = atomicAdd(&d_gbar[id], 1u);
        unsigned target = (old / (unsigned)CSRB + 1u) * (unsigned)CSRB;
        unsigned v;
        do {
            asm volatile("ld.global.acquire.gpu.b32 %0, [%1];" : "=r"(v) : "l"(&d_gbar[id]));
        } while (v < target);
    }
    __syncthreads();
}

__device__ __forceinline__ int edge_id(const void* ei, int which, int e) {
    if (d_is64) return (int)((const long long*)ei)[(size_t)which * EE + e];
    return ((const int*)ei)[(size_t)which * EE + e];
}

// -------- weight prep: transpose + bf16 hi/lo split (WT[n][k] = W[k][n]) ---------
__global__ void k_prep_w(const float* __restrict__ W1l, const float* __restrict__ W1r,
                         const float* __restrict__ W2l, const float* __restrict__ W2r) {
    int idx = blockIdx.x * blockDim.x + threadIdx.x;
    if (idx < 256 * 128) {
        int n = idx >> 7, k = idx & 127;
        float w = (n < 128) ? W1l[k * 128 + n] : W1r[k * 128 + (n - 128)];
        unsigned short h = bf16rne(w);
        ((unsigned short*)d_wt1h4)[idx] = h;
        ((unsigned short*)d_wt1lo4)[idx] = bf16rne(w - bf16tof(h));
    }
    if (idx < 128 * 128) {
        int n = idx >> 7, k = idx & 127;
        float w = (n < 64) ? W2l[k * 64 + n] : W2r[k * 64 + (n - 64)];
        unsigned short h = bf16rne(w);
        ((unsigned short*)d_wt2h4)[idx] = h;
        ((unsigned short*)d_wt2lo4)[idx] = bf16rne(w - bf16tof(h));
    }
}

// ---------------- mma.sync bf16-split GEMM body (shared by fused l1 + l2) ----------------
// which==0: D[NN,256] = x @ [W1l|W1r]; nBase=0 -> t1l (fp16), 128 -> t1r (fp32)
// which==1: D[NN,128] = h1 @ [W2l|W2r]; cols<64 -> t2l (fp16), else t2r (fp32)
__device__ __forceinline__ void gemm_body(const float* __restrict__ A,
                                          const unsigned short* __restrict__ WTh,
                                          const unsigned short* __restrict__ WTl,
                                          int which, int rowBase, int nBase) {
    __shared__ __align__(16) unsigned short sAh[128 * TS];
    __shared__ __align__(16) unsigned short sAl[128 * TS];
    __shared__ __align__(16) unsigned short sBh[128 * TS];
    __shared__ __align__(16) unsigned short sBl[128 * TS];

    int tid = threadIdx.x;
    int wid = tid >> 5;
    int lane = tid & 31;
    int wm = wid >> 2;
    int wn = wid & 3;

    float acc[4][4][4];
#pragma unroll
    for (int mi = 0; mi < 4; mi++)
#pragma unroll
        for (int ni = 0; ni < 4; ni++)
#pragma unroll
            for (int q = 0; q < 4; q++) acc[mi][ni][q] = 0.f;

    unsigned bAh = smem_u32(sAh), bAl = smem_u32(sAl);
    unsigned bBh = smem_u32(sBh), bBl = smem_u32(sBl);

    int frow = tid >> 1;
    int fcol = (tid & 1) * 16;
    int grow = rowBase + frow;

    for (int kk = 0; kk < 128; kk += 32) {
        {
            float t[16];
            if (grow < NN) {
                const float4* src = (const float4*)(A + (size_t)grow * 128 + kk + fcol);
#pragma unroll
                for (int i = 0; i < 4; i++) {
                    float4 v = src[i];
                    t[i * 4 + 0] = v.x; t[i * 4 + 1] = v.y;
                    t[i * 4 + 2] = v.z; t[i * 4 + 3] = v.w;
                }
            } else {
#pragma unroll
                for (int i = 0; i < 16; i++) t[i] = 0.f;
            }
            unsigned short hb[16], lb[16];
#pragma unroll
            for (int i = 0; i < 16; i++) {
                hb[i] = bf16rne(t[i]);
                lb[i] = bf16rne(t[i] - bf16tof(hb[i]));
            }
            uint4* dh = (uint4*)&sAh[frow * TS + fcol];
            uint4* dl = (uint4*)&sAl[frow * TS + fcol];
            dh[0] = ((uint4*)hb)[0]; dh[1] = ((uint4*)hb)[1];
            dl[0] = ((uint4*)lb)[0]; dl[1] = ((uint4*)lb)[1];
        }
        {
            const uint4* sh = (const uint4*)(WTh + (size_t)(nBase + frow) * 128 + kk + fcol);
            const uint4* sl = (const uint4*)(WTl + (size_t)(nBase + frow) * 128 + kk + fcol);
            uint4* dh = (uint4*)&sBh[frow * TS + fcol];
            uint4* dl = (uint4*)&sBl[frow * TS + fcol];
            dh[0] = sh[0]; dh[1] = sh[1];
            dl[0] = sl[0]; dl[1] = sl[1];
        }
        __syncthreads();

#pragma unroll
        for (int ks = 0; ks < 32; ks += 16) {
            unsigned aH[4][4], aL[4][4];
#pragma unroll
            for (int mi = 0; mi < 4; mi++) {
                int row = wm * 64 + mi * 16 + (lane & 15);
                int col = ks + (lane >> 4) * 8;
                unsigned off = (unsigned)(row * TS + col) * 2;
                ldm_x4(aH[mi], bAh + off);
                ldm_x4(aL[mi], bAl + off);
            }
            unsigned bH[4][2], bL[4][2];
#pragma unroll
            for (int nip = 0; nip < 4; nip += 2) {
                int nrow = wn * 32 + nip * 8 + ((lane >> 4) & 1) * 8 + (lane & 7);
                int kcol = ks + ((lane >> 3) & 1) * 8;
                unsigned off = (unsigned)(nrow * TS + kcol) * 2;
                unsigned r[4];
                ldm_x4(r, bBh + off);
                bH[nip][0] = r[0]; bH[nip][1] = r[1];
                bH[nip + 1][0] = r[2]; bH[nip + 1][1] = r[3];
                ldm_x4(r, bBl + off);
                bL[nip][0] = r[0]; bL[nip][1] = r[1];
                bL[nip + 1][0] = r[2]; bL[nip + 1][1] = r[3];
            }
#pragma unroll
            for (int mi = 0; mi < 4; mi++)
#pragma unroll
                for (int ni = 0; ni < 4; ni++) {
                    mma16816(acc[mi][ni], aH[mi], bH[ni][0], bH[ni][1]);
                    mma16816(acc[mi][ni], aL[mi], bH[ni][0], bH[ni][1]);
                    mma16816(acc[mi][ni], aH[mi], bL[ni][0], bL[ni][1]);
                }
        }
        __syncthreads();
    }

#pragma unroll
    for (int mi = 0; mi < 4; mi++) {
        int r0 = rowBase + wm * 64 + mi * 16 + (lane >> 2);
#pragma unroll
        for (int ni = 0; ni < 4; ni++) {
            int cl = wn * 32 + ni * 8 + (lane & 3) * 2;
            if (!which) {
                if (nBase == 0) {
                    // t1l fp16
                    if (r0 < NN)
                        d_t1l_h[(size_t)r0 * 64 + (cl >> 1)] =
                            __floats2half2_rn(acc[mi][ni][0], acc[mi][ni][1]);
                    if (r0 + 8 < NN)
                        d_t1l_h[(size_t)(r0 + 8) * 64 + (cl >> 1)] =
                            __floats2half2_rn(acc[mi][ni][2], acc[mi][ni][3]);
                } else {
                    float* dst = (float*)d_t1r;
                    if (r0 < NN)
                        *(float2*)(dst + (size_t)r0 * 128 + cl) =
                            make_float2(acc[mi][ni][0], acc[mi][ni][1]);
                    if (r0 + 8 < NN)
                        *(float2*)(dst + (size_t)(r0 + 8) * 128 + cl) =
                            make_float2(acc[mi][ni][2], acc[mi][ni][3]);
                }
            } else {
                if (cl < 64) {
                    // t2l fp16
                    if (r0 < NN)
                        d_t2l_h[(size_t)r0 * 32 + (cl >> 1)] =
                            __floats2half2_rn(acc[mi][ni][0], acc[mi][ni][1]);
                    if (r0 + 8 < NN)
                        d_t2l_h[(size_t)(r0 + 8) * 32 + (cl >> 1)] =
                            __floats2half2_rn(acc[mi][ni][2], acc[mi][ni][3]);
                } else {
                    float* base = (float*)d_t2r + (cl - 64);
                    if (r0 < NN)
                        *(float2*)(base + (size_t)r0 * 64) =
                            make_float2(acc[mi][ni][0], acc[mi][ni][1]);
                    if (r0 + 8 < NN)
                        *(float2*)(base + (size_t)(r0 + 8) * 64) =
                            make_float2(acc[mi][ni][2], acc[mi][ni][3]);
                }
            }
        }
    }
}

// ---------------- fused kernel: CSR build (blocks 0..147) + layer1 GEMM (rest) ------------
// NOTE: no launch_bounds — R13 showed the 128-reg cap costs ~7us on this kernel.
__global__ void k_fused(const float* __restrict__ x, const void* __restrict__ ei) {
    int bid = blockIdx.x;
    if (bid >= CSRB) {
        int gb = bid - CSRB;
        gemm_body(x, (const unsigned short*)d_wt1h4, (const unsigned short*)d_wt1lo4,
                  0, (gb >> 1) * 128, (gb & 1) * 128);
        return;
    }
    // ---------------- CSR role ----------------
    __shared__ int s[256];
    int tid = threadIdx.x;
    const int NT = CSRB * 256;
    int g = bid * 256 + tid;

    // phase A: zero counters; block 0 probes edge dtype
    for (int i = g; i < NN; i += NT) { d_cnt[i] = 0; d_cursor[i] = 0; }
    if (bid == 0) {
        __shared__ int nonzero;
        if (tid == 0) nonzero = 0;
        __syncthreads();
        const int* e32 = (const int*)ei;
        for (int j = tid; j < 4096; j += 256)
            if (e32[2 * j + 1] != 0) nonzero = 1;
        __syncthreads();
        if (tid == 0) d_is64 = (nonzero == 0) ? 1 : 0;
    }
    grid_bar(0);

    // phase B: degree count
    for (int e = g; e < EE; e += NT)
        atomicAdd(&d_cnt[edge_id(ei, 1, e)], 1);
    grid_bar(1);

    // phase C: per-segment exclusive scan (segments of 256)
    for (int seg = bid; seg < NSEG; seg += CSRB) {
        int i = seg * 256 + tid;
        int v = (i < NN) ? d_cnt[i] : 0;
        s[tid] = v;
        __syncthreads();
        for (int off = 1; off < 256; off <<= 1) {
            int t2 = (tid >= off) ? s[tid - off] : 0;
            __syncthreads();
            s[tid] += t2;
            __syncthreads();
        }
        if (i < NN) d_rowptr[i] = s[tid] - v;
        if (tid == 255) d_bsum[seg] = s[255];
        __syncthreads();
    }
    grid_bar(2);

    // phase D: redundant scan of segment sums + apply prefix
    s[tid] = (tid < NSEG) ? d_bsum[tid] : 0;
    __syncthreads();
    for (int off = 1; off < 256; off <<= 1) {
        int t2 = (tid >= off) ? s[tid - off] : 0;
        __syncthreads();
        s[tid] += t2;
        __syncthreads();
    }
    for (int seg = bid; seg < NSEG; seg += CSRB) {
        int prefix = (seg == 0) ? 0 : s[seg - 1];
        int i = seg * 256 + tid;
        if (i < NN) d_rowptr[i] += prefix;
    }
    if (bid == 0 && tid == 0) d_rowptr[NN] = EE;
    grid_bar(3);

    // phase E: fill columns
    for (int e = g; e < EE; e += NT) {
        int d = edge_id(ei, 1, e);
        int sc = edge_id(ei, 0, e);
        int p = atomicAdd(&d_cursor[d], 1);
        d_col[d_rowptr[d] + p] = sc;
    }
}

// ---------------- layer2 GEMM launcher (occ-2 cap: measured win on this kernel) -----------
__global__ void __launch_bounds__(256, 2) k_gemm_l2() {
    gemm_body((const float*)d_h1, (const unsigned short*)d_wt2h4,
              (const unsigned short*)d_wt2lo4, 1, blockIdx.x * 128, 0);
}

// ---------- layer1 agg: h1 = relu(mean_nbr(t1l fp16) + t1r[self] + b1l); warp/node --------
__global__ void k_agg1(const float* __restrict__ b1l) {
    int idx = blockIdx.x * blockDim.x + threadIdx.x;
    int node = idx >> 5;
    int lane = idx & 31;
    if (node >= NN) return;
    int beg = d_rowptr[node], end = d_rowptr[node + 1];
    float4 acc = make_float4(0.f, 0.f, 0.f, 0.f);
    for (int j = beg; j < end; j++) {
        int s = d_col[j];
        // lane covers cols lane*4..lane*4+3 = half2 idx lane*2, lane*2+1 (8B load)
        const __half2* row = d_t1l_h + (size_t)s * 64 + lane * 2;
        float2 f0 = __half22float2(row[0]);
        float2 f1 = __half22float2(row[1]);
        acc.x += f0.x; acc.y += f0.y; acc.z += f1.x; acc.w += f1.y;
    }
    int c = end - beg;
    float inv = 1.0f / (float)(c > 0 ? c : 1);
    float4 self = d_t1r[(size_t)node * 32 + lane];
    float4 b = ((const float4*)b1l)[lane];
    float4 o;
    o.x = fmaxf(acc.x * inv + self.x + b.x, 0.f);
    o.y = fmaxf(acc.y * inv + self.y + b.y, 0.f);
    o.z = fmaxf(acc.z * inv + self.z + b.z, 0.f);
    o.w = fmaxf(acc.w * inv + self.w + b.w, 0.f);
    d_h1[(size_t)node * 32 + lane] = o;
}

// ------- layer2 agg + bias + softmax: h2 = softmax(mean_nbr(t2l fp16) + t2r + b2l) --------
__global__ void k_agg2sm(const float* __restrict__ b2l) {
    int idx = blockIdx.x * blockDim.x + threadIdx.x;
    int node = idx >> 5;
    int lane = idx & 31;
    if (node >= NN) return;
    int beg = d_rowptr[node], end = d_rowptr[node + 1];
    float ax = 0.f, ay = 0.f;
    for (int j = beg; j < end; j++) {
        int s = d_col[j];
        float2 f = __half22float2(d_t2l_h[(size_t)s * 32 + lane]);
        ax += f.x; ay += f.y;
    }
    int c = end - beg;
    float inv = 1.0f / (float)(c > 0 ? c : 1);
    float2 self = ((const float2*)d_t2r)[(size_t)node * 32 + lane];
    float2 b = ((const float2*)b2l)[lane];
    float vx = ax * inv + self.x + b.x;
    float vy = ay * inv + self.y + b.y;
    float m = fmaxf(vx, vy);
    for (int o = 16; o > 0; o >>= 1) m = fmaxf(m, __shfl_xor_sync(0xffffffffu, m, o));
    float ex = __expf(vx - m), ey = __expf(vy - m);
    float sum = ex + ey;
    for (int o = 16; o > 0; o >>= 1) sum += __shfl_xor_sync(0xffffffffu, sum, o);
    float is = 1.0f / sum;
    ((float2*)d_h2)[(size_t)node * 32 + lane] = make_float2(ex * is, ey * is);
}

// ---------------- GCN GEMM (FFMA): y = (h2 @ Wg) * dinv[row]; M=NN, N=64, K=64 ------------
__global__ void __launch_bounds__(256) k_gemm_gcn(const float* __restrict__ Wg) {
    __shared__ float As[64][17];
    __shared__ float Ws[16][64];
    int tid = threadIdx.x;
    int rowBase = blockIdx.x * 64;
    int rg = tid >> 4;
    int cg = tid & 15;
    float acc[4][4];
#pragma unroll
    for (int i = 0; i < 4; i++)
#pragma unroll
        for (int j = 0; j < 4; j++) acc[i][j] = 0.f;

    int lr = tid >> 2;
    int lc = (tid & 3) * 4;
    bool lvalid = (rowBase + lr) < NN;
    const float* A = (const float*)d_h2;

    for (int kk = 0; kk < 64; kk += 16) {
        float4 va = make_float4(0.f, 0.f, 0.f, 0.f);
        if (lvalid) va = *(const float4*)(A + (size_t)(rowBase + lr) * 64 + kk + lc);
        As[lr][lc + 0] = va.x; As[lr][lc + 1] = va.y;
        As[lr][lc + 2] = va.z; As[lr][lc + 3] = va.w;
        {
            int wr = tid >> 4;
            int wc = (tid & 15) * 4;
            *(float4*)&Ws[wr][wc] = *(const float4*)(Wg + (size_t)(kk + wr) * 64 + wc);
        }
        __syncthreads();
#pragma unroll
        for (int k = 0; k < 16; k++) {
            float4 bv = *(const float4*)&Ws[k][cg * 4];
#pragma unroll
            for (int i = 0; i < 4; i++) {
                float a = As[rg * 4 + i][k];
                acc[i][0] += a * bv.x;
                acc[i][1] += a * bv.y;
                acc[i][2] += a * bv.z;
                acc[i][3] += a * bv.w;
            }
        }
        __syncthreads();
    }
#pragma unroll
    for (int i = 0; i < 4; i++) {
        int r = rowBase + rg * 4 + i;
        if (r < NN) {
            float dinv = rsqrtf((float)(d_cnt[r] + 1));
            float4 v = make_float4(acc[i][0] * dinv, acc[i][1] * dinv,
                                   acc[i][2] * dinv, acc[i][3] * dinv);
            d_y[(size_t)r * 16 + cg] = v;
        }
    }
}

// ---------------- GCN aggregation: out[i] = dinv[i]*(y[i] + sum_nbr y[j]) + bg ------------
__global__ void k_gcn_agg(const float* __restrict__ bg, float* __restrict__ out) {
    int idx = blockIdx.x * blockDim.x + threadIdx.x;
    int node = idx >> 4;
    int lane = idx & 15;
    if (node >= NN) return;
    float4 acc = d_y[(size_t)node * 16 + lane];
    int beg = d_rowptr[node], end = d_rowptr[node + 1];
    for (int j = beg; j < end; j++) {
        int s = d_col[j];
        float4 v = d_y[(size_t)s * 16 + lane];
        acc.x += v.x; acc.y += v.y; acc.z += v.z; acc.w += v.w;
    }
    float dinv = rsqrtf((float)(d_cnt[node] + 1));
    float4 b = ((const float4*)bg)[lane];
    float4 o;
    o.x = acc.x * dinv + b.x;
    o.y = acc.y * dinv + b.y;
    o.z = acc.z * dinv + b.z;
    o.w = acc.w * dinv + b.w;
    ((float4*)out)[(size_t)node * 16 + lane] = o;
}

// ---------------- launch ----------------
extern "C" void kernel_launch(void* const* d_in, const int* in_sizes, int n_in,
                              void* d_out, int out_size) {
    const float* x = (const float*)d_in[0];
    const void* ei = d_in[1];
    const float* W1l = (const float*)d_in[2];
    const float* b1l = (const float*)d_in[3];
    const float* W1r = (const float*)d_in[4];
    const float* W2l = (const float*)d_in[5];
    const float* b2l = (const float*)d_in[6];
    const float* W2r = (const float*)d_in[7];
    const float* Wg  = (const float*)d_in[8];
    const float* bg  = (const float*)d_in[9];
    float* out = (float*)d_out;

    const int GT = (NN + 127) / 128;  // 391

    // weight prep, then fused CSR-build + layer1 GEMM (CSR hidden under GEMM)
    k_prep_w<<<128, 256>>>(W1l, W1r, W2l, W2r);
    k_fused<<<CSRB + GT * 2, 256>>>(x, ei);

    // layer 1 epilogue: fused agg + bias + relu (fat grid; fp16 gather = half traffic)
    k_agg1<<<(NN * 32 + 255) / 256, 256>>>(b1l);

    // layer 2: mma GEMM (occ-2 cap), then fat-grid agg + bias + softmax (fp16 gather)
    k_gemm_l2<<<GT, 256>>>();
    k_agg2sm<<<(NN * 32 + 255) / 256, 256>>>(b2l);

    // GCN: y = (h2 @ Wg) * dinv (FFMA, thin grid), then normalized aggregation + bias
    k_gemm_gcn<<<(NN + 63) / 64, 256>>>(Wg);
    k_gcn_agg<<<(NN * 16 + 255) / 256, 256>>>(bg, out);
}